// round 16
// baseline (speedup 1.0000x reference)
#include <cuda_runtime.h>
#include <math.h>

#define F      16
#define E0C    90112
#define N0C    1408
#define GRID   128
#define BLOCK  768
#define NWARPS (BLOCK / 32)      // 24
#define NT     (GRID * BLOCK)    // 98304
#define GEMM0  (N0C * F)         // 22528
#define CAP3   2560

// ---------------- persistent device state ----------------
__device__ unsigned int g_arrive;
__device__ unsigned int g_gen;             // monotonic generation
__device__ int g_c1, g_c2;                 // compacted edge counts (layers 1,2)
__device__ __align__(16) float g_h   [N0C * F];
__device__ __align__(16) float g_outA[N0C * F];   // O_0, reused as O_2
__device__ __align__(16) float g_outB[704 * F];   // O_1
__device__ __align__(16) float g_out3[176 * F];   // O_3
__device__ float g_deg0[N0C];
__device__ float g_deg1[704];
__device__ float g_deg2[352];
__device__ int   g_pos [N0C];
__device__ int2  g_e0[E0C];
__device__ int2  g_e1[E0C];
__device__ int2  g_e2[E0C];
__device__ float g_h1[1024];

// ---------------- flat grid barrier (R4-proven) ----------------
__device__ __forceinline__ void gsync() {
    __syncthreads();
    if (threadIdx.x == 0) {
        unsigned int gen;
        asm volatile("ld.acquire.gpu.u32 %0, [%1];" : "=r"(gen) : "l"(&g_gen) : "memory");
        unsigned int old;
        asm volatile("atom.add.release.gpu.u32 %0, [%1], 1;"
                     : "=r"(old) : "l"(&g_arrive) : "memory");
        if (old == GRID - 1u) {
            asm volatile("st.relaxed.gpu.u32 [%0], 0;" :: "l"(&g_arrive) : "memory");
            asm volatile("st.release.gpu.u32 [%0], %1;" :: "l"(&g_gen), "r"(gen + 1u) : "memory");
        } else {
            unsigned int cur;
            do {
                asm volatile("ld.acquire.gpu.u32 %0, [%1];" : "=r"(cur) : "l"(&g_gen) : "memory");
            } while (cur == gen);
        }
    }
    __syncthreads();
}

__device__ __forceinline__ void red_add_v4(float* addr, float a, float b, float c, float d) {
    asm volatile("red.global.add.v4.f32 [%0], {%1, %2, %3, %4};"
                 :: "l"(addr), "f"(a), "f"(b), "f"(c), "f"(d) : "memory");
}

__device__ __forceinline__ unsigned long long score_key(const float* __restrict__ outL,
                                                        const float* __restrict__ bb,
                                                        const float* __restrict__ pw,
                                                        float npw, int i) {
    float s = 0.0f;
    #pragma unroll
    for (int f = 0; f < F; f++) {
        float v = outL[i * F + f] + bb[f];
        v = v > 0.0f ? v : 0.0f;
        s += v * pw[f];
    }
    float sc = tanhf(s / npw);
    int bits = __float_as_int(sc);
    unsigned int ka = (bits >= 0) ? (0x80000000u + (unsigned int)bits)
                                  : ~(unsigned int)bits;
    return ((unsigned long long)(~ka) << 32) | (unsigned int)i;
}

__device__ __forceinline__ float key_val(unsigned long long key) {
    unsigned int ka = ~(unsigned int)(key >> 32);
    int bits = (ka >= 0x80000000u) ? (int)(ka - 0x80000000u) : (int)(~ka);
    return __int_as_float(bits);
}

__device__ __forceinline__ float pw_norm(const float* __restrict__ pw) {
    float npw = 0.0f;
    #pragma unroll
    for (int f = 0; f < F; f++) { float v = pw[f]; npw += v * v; }
    return sqrtf(npw);
}

// distributed scatter: self-loops + edges, RED into global accum
__device__ __forceinline__ void scatter_g(const float* __restrict__ h,
                                          const int2* __restrict__ el, int C,
                                          const float* __restrict__ deg,
                                          float* __restrict__ ob, int n, int gtid) {
    for (int t = gtid; t < n + C; t += NT) {
        const float4* hr; float* oc; float norm;
        if (t < n) {
            norm = 1.0f / (deg[t] + 1.0f);
            hr = (const float4*)&h[t * F]; oc = &ob[t * F];
        } else {
            int2 rc = el[t - n];
            norm = __frsqrt_rn(deg[rc.x] + 1.0f) * __frsqrt_rn(deg[rc.y] + 1.0f);
            hr = (const float4*)&h[rc.x * F]; oc = &ob[rc.y * F];
        }
        #pragma unroll
        for (int q = 0; q < 4; q++) {
            float4 hv = hr[q];
            red_add_v4(oc + 4 * q, norm * hv.x, norm * hv.y, norm * hv.z, norm * hv.w);
        }
    }
}

// distributed pool: rank own warp's node, fused gather+gemm into hdst, zero outN
__device__ __forceinline__ void pool_dist(const float* __restrict__ outL,
                                          const float* __restrict__ bb,
                                          const float* __restrict__ pw,
                                          const float* __restrict__ Wn,
                                          float* __restrict__ outN,
                                          float* __restrict__ hdst,
                                          int n, int K,
                                          unsigned long long* s_keys,
                                          int tid, int lane, int wid, int bx) {
    if (bx * NWARPS >= n) return;
    float npw = pw_norm(pw);
    for (int i = tid; i < n; i += BLOCK) s_keys[i] = score_key(outL, bb, pw, npw, i);
    __syncthreads();
    int i = bx * NWARPS + wid;
    if (i < n) {
        unsigned long long ki = s_keys[i];
        int cnt = 0;
        for (int j = lane; j < n; j += 32) cnt += (s_keys[j] < ki) ? 1 : 0;
        int rank = __reduce_add_sync(0xFFFFFFFFu, cnt);
        if (rank < K) {
            float val = key_val(ki);
            if (lane == 0) g_pos[i] = rank;
            if (lane < F) {
                float acc = 0.0f;
                #pragma unroll
                for (int f = 0; f < F; f++) {
                    float v = outL[i * F + f] + bb[f];
                    v = v > 0.0f ? v : 0.0f;
                    acc += v * Wn[f * F + lane];
                }
                hdst[rank * F + lane] = acc * val;
                outN[rank * F + lane] = 0.0f;
            }
        } else if (lane == 0) {
            g_pos[i] = -1;
        }
    }
    __syncthreads();
}

// distributed edge remap + compact + degree
__device__ __forceinline__ void remap_dist(const int2* __restrict__ ein, int C,
                                           int2* __restrict__ eout, int* pcnt,
                                           float* __restrict__ degout,
                                           int gtid, int lane) {
    int iters = (C + NT - 1) / NT;
    for (int it = 0; it < iters; it++) {
        int e = it * NT + gtid;
        bool valid = false; int nr = 0, nc = 0;
        if (e < C) {
            int2 rc = ein[e];
            nr = g_pos[rc.x]; nc = g_pos[rc.y];
            valid = (nr >= 0) && (nc >= 0);
        }
        unsigned int m = __ballot_sync(0xFFFFFFFFu, valid);
        if (m) {
            int leader = __ffs(m) - 1;
            int base = 0;
            if (lane == leader) base = atomicAdd(pcnt, __popc(m));
            base = __shfl_sync(0xFFFFFFFFu, base, leader);
            if (valid) {
                int pp = base + __popc(m & ((1u << lane) - 1u));
                eout[pp] = make_int2(nr, nc);
                atomicAdd(&degout[nc], 1.0f);
            }
        }
    }
}

__global__ void __launch_bounds__(BLOCK, 1) gcn_fused(
    const float* __restrict__ x, const int* __restrict__ ei,
    const float* __restrict__ W0, const float* __restrict__ b0,
    const float* __restrict__ W1, const float* __restrict__ b1,
    const float* __restrict__ W2, const float* __restrict__ b2,
    const float* __restrict__ W3, const float* __restrict__ b3,
    const float* __restrict__ pw0, const float* __restrict__ pw1,
    const float* __restrict__ pw2, const float* __restrict__ pw3,
    const float* __restrict__ fw1, const float* __restrict__ fb1,
    const float* __restrict__ fw2, const float* __restrict__ fb2,
    const float* __restrict__ fw3, const float* __restrict__ fb3,
    float* __restrict__ out)
{
    const int tid  = threadIdx.x;
    const int gtid = blockIdx.x * BLOCK + tid;
    const int lane = tid & 31;
    const int wid  = tid >> 5;
    const int bx   = blockIdx.x;

    __shared__ __align__(16) unsigned long long s_keys[N0C];  // 11.3 KB
    __shared__ __align__(16) float s_h3[176 * F];             // 11.3 KB
    __shared__ unsigned int s_e3[CAP3];                       // 10.2 KB
    __shared__ short  s_pos2[352];
    __shared__ short  s_perm[176];
    __shared__ float  s_val [176];
    __shared__ float  s_deg3[176];
    __shared__ int    s_scan[NWARPS + 1];

    // ================= Phase M (balanced: one gemm task per thread; edges elsewhere) ====
    if (gtid < GEMM0) {
        int i = gtid >> 4, j = gtid & 15;
        const float* xr = x + i * 128;
        float acc = 0.0f;
        #pragma unroll 16
        for (int k = 0; k < 128; k++) acc += xr[k] * W0[k * F + j];
        g_h[gtid] = acc;
        g_outA[gtid] = 0.0f;
    } else {
        for (int e = gtid - GEMM0; e < E0C; e += NT - GEMM0) {   // 75776 threads, 1-2 each
            int r = ei[e], c = ei[E0C + e];
            g_e0[e] = make_int2(r, c);
            atomicAdd(&g_deg0[c], 1.0f);
        }
    }
    if (gtid < 1024) g_h1[gtid] = fb1[gtid];
    if (gtid < 96)   out[gtid]  = fb3[gtid];
    if (gtid == 0) { g_c1 = 0; g_c2 = 0; }
    gsync();

    // ================= S0 =================
    scatter_g(g_h, g_e0, E0C, g_deg0, g_outA, N0C, gtid);
    gsync();

    // ================= P0 (+ clean deg0) =================
    for (int i = gtid; i < N0C; i += NT) g_deg0[i] = 0.0f;
    pool_dist(g_outA, b0, pw0, W1, g_outB, g_h, N0C, 704, s_keys, tid, lane, wid, bx);
    gsync();

    // ================= E0 =================
    remap_dist(g_e0, E0C, g_e1, &g_c1, g_deg1, gtid, lane);
    gsync();

    // ================= S1 =================
    {
        int C1 = g_c1;
        scatter_g(g_h, g_e1, C1, g_deg1, g_outB, 704, gtid);
    }
    gsync();

    // ================= P1 (+ clean deg1) =================
    for (int i = gtid; i < 704; i += NT) g_deg1[i] = 0.0f;
    pool_dist(g_outB, b1, pw1, W2, g_outA, g_h, 704, 352, s_keys, tid, lane, wid, bx);
    gsync();

    // ================= E1 =================
    {
        int C1 = g_c1;
        remap_dist(g_e1, C1, g_e2, &g_c2, g_deg2, gtid, lane);
    }
    gsync();

    // ================= S2 (+ zero O3) =================
    {
        int C2 = g_c2;
        scatter_g(g_h, g_e2, C2, g_deg2, g_outA, 352, gtid);
        if (gtid < 176 * F) g_out3[gtid] = 0.0f;
    }
    gsync();

    // ================= merged P2+E2+S3 (redundant per block; deterministic scan) =========
    {
        for (int i = gtid; i < 352; i += NT) g_deg2[i] = 0.0f;   // self-clean

        // a) rank all 352 nodes locally
        float npw = pw_norm(pw2);
        for (int i = tid; i < 352; i += BLOCK)
            s_keys[i] = score_key(g_outA, b2, pw2, npw, i);
        if (tid < 176) s_deg3[tid] = 0.0f;
        __syncthreads();
        for (int i = wid; i < 352; i += NWARPS) {
            unsigned long long ki = s_keys[i];
            int cnt = 0;
            for (int j = lane; j < 352; j += 32) cnt += (s_keys[j] < ki) ? 1 : 0;
            int rank = __reduce_add_sync(0xFFFFFFFFu, cnt);
            if (lane == 0) {
                if (rank < 176) {
                    s_pos2[i] = (short)rank;
                    s_perm[rank] = (short)i;
                    s_val[rank] = key_val(ki);
                } else s_pos2[i] = -1;
            }
        }
        __syncthreads();

        // b) deterministic two-pass compaction of g_e2 -> s_e3 (identical in every block)
        int C2 = g_c2;
        int seg = (C2 + BLOCK - 1) / BLOCK;
        int e0 = tid * seg, e1 = min(e0 + seg, C2);
        int mycnt = 0;
        for (int e = e0; e < e1; e++) {
            int2 rc = g_e2[e];
            if (s_pos2[rc.x] >= 0 && s_pos2[rc.y] >= 0) mycnt++;
        }
        int pre = mycnt;
        #pragma unroll
        for (int d = 1; d < 32; d <<= 1) {
            int t = __shfl_up_sync(0xFFFFFFFFu, pre, d);
            if (lane >= d) pre += t;
        }
        if (lane == 31) s_scan[wid] = pre;
        __syncthreads();
        if (tid == 0) {
            int acc = 0;
            #pragma unroll
            for (int w = 0; w < NWARPS; w++) { int t = s_scan[w]; s_scan[w] = acc; acc += t; }
            s_scan[NWARPS] = acc;
        }
        __syncthreads();
        int base = s_scan[wid] + (pre - mycnt);
        int C3 = min(s_scan[NWARPS], CAP3);
        for (int e = e0; e < e1; e++) {
            int2 rc = g_e2[e];
            short nr = s_pos2[rc.x], nc = s_pos2[rc.y];
            if (nr >= 0 && nc >= 0) {
                if (base < CAP3)
                    s_e3[base] = (unsigned int)(unsigned short)nr |
                                 ((unsigned int)(unsigned short)nc << 16);
                atomicAdd(&s_deg3[nc], 1.0f);
                base++;
            }
        }
        __syncthreads();

        // c) h3 = X2 @ W3 (warp shfl-gemm) into smem
        {
            float w[16];
            int f2 = lane & 15;
            #pragma unroll
            for (int f = 0; f < 16; f++) w[f] = W3[f * F + f2];
            int sub = lane >> 4;
            for (int j0 = wid * 2; j0 < 176; j0 += NWARPS * 2) {
                int j = j0 + sub;
                int p = s_perm[j];
                float val = s_val[j];
                int f = lane & 15;
                float v = g_outA[p * F + f] + b2[f];
                v = v > 0.0f ? v : 0.0f;
                float acc = 0.0f;
                #pragma unroll
                for (int fk = 0; fk < 16; fk++)
                    acc += __shfl_sync(0xFFFFFFFFu, v, (sub << 4) + fk) * w[fk];
                s_h3[j * F + f2] = acc * val;
            }
        }
        __syncthreads();

        // d) scatter this block's slice (thread-partitioned) into global O3
        {
            int total = 176 + C3;
            int chunk = (total + GRID - 1) / GRID;
            int t0 = bx * chunk, t1 = min(t0 + chunk, total);
            for (int t = t0 + tid; t < t1; t += BLOCK) {
                const float4* hr; float* oc; float norm;
                if (t < 176) {
                    norm = 1.0f / (s_deg3[t] + 1.0f);
                    hr = (const float4*)&s_h3[t * F]; oc = &g_out3[t * F];
                } else {
                    unsigned int pk = s_e3[t - 176];
                    int r = pk & 0xFFFF, c = pk >> 16;
                    norm = __frsqrt_rn(s_deg3[r] + 1.0f) * __frsqrt_rn(s_deg3[c] + 1.0f);
                    hr = (const float4*)&s_h3[r * F]; oc = &g_out3[c * F];
                }
                #pragma unroll
                for (int q = 0; q < 4; q++) {
                    float4 hv = hr[q];
                    red_add_v4(oc + 4 * q, norm * hv.x, norm * hv.y, norm * hv.z, norm * hv.w);
                }
            }
        }
    }
    gsync();

    // ================= merged P3 + FC1 =================
    {
        float npw = pw_norm(pw3);
        for (int i = tid; i < 176; i += BLOCK)
            s_keys[i] = score_key(g_out3, b3, pw3, npw, i);
        __syncthreads();
        for (int i = wid; i < 176; i += NWARPS) {
            unsigned long long ki = s_keys[i];
            int cnt = 0;
            for (int j = lane; j < 176; j += 32) cnt += (s_keys[j] < ki) ? 1 : 0;
            int rank = __reduce_add_sync(0xFFFFFFFFu, cnt);
            if (rank < 88 && lane == 0) { s_perm[rank] = (short)i; s_val[rank] = key_val(ki); }
        }
        __syncthreads();

        const int i0 = bx * 11;
        float vin[11];
        #pragma unroll
        for (int q = 0; q < 11; q++) {
            int i = i0 + q, j = i >> 4, f = i & 15;
            float v = g_out3[s_perm[j] * F + f] + b3[f];
            v = v > 0.0f ? v : 0.0f;
            vin[q] = v * s_val[j];
        }
        for (int o = tid; o < 1024; o += BLOCK) {
            float acc = 0.0f;
            #pragma unroll
            for (int q = 0; q < 11; q++) acc += vin[q] * fw1[(i0 + q) * 1024 + o];
            atomicAdd(&g_h1[o], acc);
        }
    }
    gsync();

    // ================= merged FC2+FC3 (block bx owns h2[4bx..4bx+4)) =================
    {
        __shared__ float s_part[64];    // warps 0-15 x 4 j-classes
        __shared__ float s_h2loc[4];
        int j4 = tid & 3;
        int ch = tid >> 2;              // chunk of 8 inputs; valid for ch < 128 (tid < 512)
        int jq = bx * 4 + j4;
        float acc = 0.0f;
        if (ch < 128) {
            int i0 = ch * 8;
            #pragma unroll
            for (int q = 0; q < 8; q++) acc += g_h1[i0 + q] * fw2[(i0 + q) * 512 + jq];
        }
        acc += __shfl_xor_sync(0xFFFFFFFFu, acc, 4);
        acc += __shfl_xor_sync(0xFFFFFFFFu, acc, 8);
        acc += __shfl_xor_sync(0xFFFFFFFFu, acc, 16);
        if (wid < 16 && lane < 4) s_part[wid * 4 + lane] = acc;
        __syncthreads();
        if (tid < 4) {
            float s = fb2[bx * 4 + tid];
            #pragma unroll
            for (int w = 0; w < 16; w++) s += s_part[w * 4 + tid];
            s_h2loc[tid] = s;
        }
        __syncthreads();
        if (tid < 96) {
            float acc2 = 0.0f;
            #pragma unroll
            for (int q = 0; q < 4; q++)
                acc2 += s_h2loc[q] * fw3[(bx * 4 + q) * 96 + tid];
            atomicAdd(&out[tid], acc2);
        }
    }
}

extern "C" void kernel_launch(void* const* d_in, const int* in_sizes, int n_in,
                              void* d_out, int out_size) {
    gcn_fused<<<GRID, BLOCK>>>(
        (const float*)d_in[0],  (const int*)d_in[1],
        (const float*)d_in[3],  (const float*)d_in[4],
        (const float*)d_in[5],  (const float*)d_in[6],
        (const float*)d_in[7],  (const float*)d_in[8],
        (const float*)d_in[9],  (const float*)d_in[10],
        (const float*)d_in[11], (const float*)d_in[12],
        (const float*)d_in[13], (const float*)d_in[14],
        (const float*)d_in[15], (const float*)d_in[16],
        (const float*)d_in[17], (const float*)d_in[18],
        (const float*)d_in[19], (const float*)d_in[20],
        (float*)d_out);
}